// round 4
// baseline (speedup 1.0000x reference)
#include <cuda_runtime.h>
#include <cstdint>

// PureTransformerVM: one-hot "neural ALU" collapsed to exact integer /
// piecewise-linear arithmetic.
//  - sum_byte softmax has exactly 3 output values {1, e^-50, e^-100}
//  - gates = one-hot(op_idx)
//  - div   = PWL seed + 2 Newton steps + round + correction (verbatim from
//            round-1 kernel, which matched the reference exactly)
// R3 (resubmit; prior bench died on broker infra): 2 rows per warp (one per
// half-warp) to double memory-level parallelism; half-warp-masked REDUX for
// the argmax reduces. op row load hoisted into the front batch (clamped idx).

#define NROWS 32768
#define OUT_COLS 296   // 256 sum_byte + 39 gates + 1 div

// softmax off-values (fp32-rounded). e^-100 is a subnormal (27 * 2^-149).
#define E_M50  1.9287498479639178e-22f
#define E_M100 3.7835058536770485e-44f

// one-hot argmax via dot-product with the column-index vector.
// products and sums are exact in fp32 (values 0/1 times integers < 256).
static __device__ __forceinline__ float dot_idx(float4 v, float c0) {
    return fmaf(v.x, c0,
           fmaf(v.y, c0 + 1.0f,
           fmaf(v.z, c0 + 2.0f,
                v.w * (c0 + 3.0f))));
}

// value pattern of one float4 group (4 consecutive columns) of the sum_byte
// softmax row: winner -> 1.0, shared hi- or lo-nibble -> e^-50, else e^-100.
static __device__ __forceinline__ float4 sum_group(int q, int sbyte, int sh, int sl) {
    const int hi  = q >> 2;
    const int lob = (q & 3) << 2;
    const int cb  = q << 2;
    float4 w;
    float* wp = (float*)&w;
    #pragma unroll
    for (int e = 0; e < 4; e++) {
        float v = ((hi == sh) || ((lob + e) == sl)) ? E_M50 : E_M100;
        v = ((cb + e) == sbyte) ? 1.0f : v;
        wp[e] = v;
    }
    return w;
}

__global__ __launch_bounds__(256)
void vm_kernel(const float4* __restrict__ a_oh,
               const float4* __restrict__ b_oh,
               const float4* __restrict__ op_oh,
               const float*  __restrict__ a_f,
               const float*  __restrict__ b_f,
               float* __restrict__ out)
{
    const int gtid = blockIdx.x * blockDim.x + threadIdx.x;
    const int warp = gtid >> 5;
    const int lane = gtid & 31;
    const int half = lane >> 4;           // 0 or 1: which row of the pair
    const int hl   = lane & 15;           // lane within half-warp
    const int row  = (warp << 1) + half;  // grid covers exactly NROWS rows

    // ---- Front-batched loads: 9 wide loads + 2 scalars in flight --------
    const float4* pa = a_oh  + (size_t)row * 64;
    const float4* pb = b_oh  + (size_t)row * 64;
    const float4* po = op_oh + (size_t)row * 64;

    float4 va[4], vb[4];
    #pragma unroll
    for (int i = 0; i < 4; i++) va[i] = pa[hl + 16 * i];
    #pragma unroll
    for (int i = 0; i < 4; i++) vb[i] = pb[hl + 16 * i];
    // op_idx < 39: only the first 40 floats (10 float4) can be hot.
    // Unpredicated load with clamped index keeps the front batch intact.
    const float4 vo_raw = po[min(hl, 9)];

    const float af = a_f[row];
    const float bf = b_f[row];

    const float4 vo = (hl < 10) ? vo_raw : make_float4(0.f, 0.f, 0.f, 0.f);

    // ---- Argmax: index dot-product (fma pipe) + half-warp add-reduce ----
    const float c0 = (float)(hl << 2);
    float ia_f = 0.f, ib_f = 0.f;
    #pragma unroll
    for (int i = 0; i < 4; i++) {
        ia_f += dot_idx(va[i], c0 + 64.0f * i);
        ib_f += dot_idx(vb[i], c0 + 64.0f * i);
    }
    const float io_f = dot_idx(vo, c0);

    const unsigned hmask = 0xFFFFu << (half << 4);
    const int ia = __reduce_add_sync(hmask, (int)ia_f);
    const int ib = __reduce_add_sync(hmask, (int)ib_f);
    const int io = __reduce_add_sync(hmask, (int)io_f);

    // ---- sum_byte index: 8-bit add (carry lo->hi, hi carry dropped) -----
    const int sbyte = (ia + ib) & 255;
    const int sh = sbyte >> 4;
    const int sl = sbyte & 15;

    // ---- div path: VERBATIM from round-1 kernel (matched exactly) -------
    float sa = (af > 0.f) ? 1.f : ((af < 0.f) ? -1.f : 0.f);
    float sb = (bf > 0.f) ? 1.f : ((bf < 0.f) ? -1.f : 0.f);
    float sg = sa * sb;
    if (sg == 0.f) sg = 1.f;

    const float aa = fabsf(af);
    const float ba = fabsf(bf);

    const float expo = floorf(log2f(ba + 1e-10f));
    const float p2   = exp2f(expo);
    const float norm = fminf(fmaxf(ba / p2, 0.5f), 0.9999f);

    int seg = (int)floorf((norm - 0.5f) * 128.0f);
    seg = max(0, min(63, seg));
    const float bpl   = 0.5f + (float)seg * 0.0078125f;
    const float vl    = 1.0f / bpl;
    const float vr    = 1.0f / (bpl + 0.0078125f);
    const float slope = (vr - vl) * 128.0f;
    float y = vl + slope * (norm - bpl);

    y = y * (2.0f - norm * y);
    y = y * (2.0f - norm * y);
    y = y / p2;

    const float result = aa * y;
    float cand = rintf(result);
    const float check = cand * ba;
    if (check > aa + 0.5f) cand -= 1.0f;
    const float divres = cand * sg;

    // ---- Write 296 floats = 74 float4 per row, streaming (evict-first) --
    // 64 sum groups: 4 per half-warp lane; tail group (gates/div) on hl<10.
    float4* pout = (float4*)(out + (size_t)row * OUT_COLS);

    #pragma unroll
    for (int i = 0; i < 4; i++) {
        const int q = hl + 16 * i;
        __stcs(&pout[q], sum_group(q, sbyte, sh, sl));
    }

    if (hl < 10) {
        const int g0 = hl << 2;            // gate index of element 0
        float4 w;
        w.x = (g0     == io) ? 1.0f : 0.0f;
        w.y = (g0 + 1 == io) ? 1.0f : 0.0f;
        w.z = (g0 + 2 == io) ? 1.0f : 0.0f;
        w.w = (hl == 9) ? divres : ((g0 + 3 == io) ? 1.0f : 0.0f);
        __stcs(&pout[64 + hl], w);
    }
}

extern "C" void kernel_launch(void* const* d_in, const int* in_sizes, int n_in,
                              void* d_out, int out_size)
{
    (void)in_sizes; (void)n_in; (void)out_size;
    const float4* a_oh  = (const float4*)d_in[0];
    const float4* b_oh  = (const float4*)d_in[1];
    const float4* op_oh = (const float4*)d_in[2];
    const float*  a_f   = (const float*)d_in[3];
    const float*  b_f   = (const float*)d_in[4];
    float* out = (float*)d_out;

    // two rows per warp: 16384 warps = 2048 blocks x 256 threads
    vm_kernel<<<2048, 256>>>(a_oh, b_oh, op_oh, a_f, b_f, out);
}

// round 5
// speedup vs baseline: 1.1352x; 1.1352x over previous
#include <cuda_runtime.h>
#include <cstdint>

// PureTransformerVM: one-hot "neural ALU" collapsed to exact integer /
// piecewise-linear arithmetic.
//  - sum_byte softmax has exactly 3 output values {1, e^-50, e^-100}
//  - gates = one-hot(op_idx)
//  - div   = PWL seed + 2 Newton steps + round + correction (verbatim from
//            round-1 kernel, which matched the reference exactly)
// R5: revert to 1 row/warp (R4's 2-row variant cost occupancy: 48 regs,
//     occ 53.8%). Single packed REDUX for all three argmaxes; unpredicated
//     clamped op load keeps the 7-load front batch unbroken.

#define NROWS 32768
#define OUT_COLS 296   // 256 sum_byte + 39 gates + 1 div

// softmax off-values (fp32-rounded). e^-100 is a subnormal (27 * 2^-149).
#define E_M50  1.9287498479639178e-22f
#define E_M100 3.7835058536770485e-44f

// one-hot argmax via dot-product with the column-index vector.
// products and sums are exact in fp32 (values 0/1 times integers < 256).
static __device__ __forceinline__ float dot_idx(float4 v, float c0) {
    return fmaf(v.x, c0,
           fmaf(v.y, c0 + 1.0f,
           fmaf(v.z, c0 + 2.0f,
                v.w * (c0 + 3.0f))));
}

// value pattern of one float4 group (4 consecutive columns) of the sum_byte
// softmax row: winner -> 1.0, shared hi- or lo-nibble -> e^-50, else e^-100.
static __device__ __forceinline__ float4 sum_group(int q, int sbyte, int sh, int sl) {
    const int hi  = q >> 2;
    const int lob = (q & 3) << 2;
    const int cb  = q << 2;
    float4 w;
    float* wp = (float*)&w;
    #pragma unroll
    for (int e = 0; e < 4; e++) {
        float v = ((hi == sh) || ((lob + e) == sl)) ? E_M50 : E_M100;
        v = ((cb + e) == sbyte) ? 1.0f : v;
        wp[e] = v;
    }
    return w;
}

__global__ __launch_bounds__(256)
void vm_kernel(const float4* __restrict__ a_oh,
               const float4* __restrict__ b_oh,
               const float4* __restrict__ op_oh,
               const float*  __restrict__ a_f,
               const float*  __restrict__ b_f,
               float* __restrict__ out)
{
    const int gtid = blockIdx.x * blockDim.x + threadIdx.x;
    const int row  = gtid >> 5;           // grid covers exactly NROWS rows
    const int lane = gtid & 31;

    // ---- Front-batched loads: 5 wide + 2 scalar loads in flight ---------
    const float4* pa = a_oh  + (size_t)row * 64;
    const float4* pb = b_oh  + (size_t)row * 64;
    const float4* po = op_oh + (size_t)row * 64;

    float4 va0 = pa[lane];
    float4 va1 = pa[lane + 32];
    float4 vb0 = pb[lane];
    float4 vb1 = pb[lane + 32];
    // op_idx < 39: only the first 40 floats (10 float4) can be hot.
    // Unpredicated clamped load (lanes >=10 broadcast group 9, zeroed below).
    float4 vo = po[min(lane, 9)];

    const float af = a_f[row];
    const float bf = b_f[row];

    // ---- Argmax: index dot-products (fma pipe), ONE packed warp reduce --
    const float c0 = (float)(lane << 2);
    const float ia_f = dot_idx(va0, c0) + dot_idx(va1, c0 + 128.0f);
    const float ib_f = dot_idx(vb0, c0) + dot_idx(vb1, c0 + 128.0f);
    const float io_f = (lane < 10) ? dot_idx(vo, c0) : 0.0f;

    // Exactly one lane holds each index; pack (ia+ib) + 1024*io (< 2^24,
    // integer-exact in fp32), one F2I + one REDUX.ADD for all three.
    const int packed = __reduce_add_sync(0xffffffffu,
                          (int)(ia_f + ib_f + 1024.0f * io_f));
    const int io   = packed >> 10;
    const int sab  = packed & 1023;

    // ---- sum_byte index: 8-bit add (carry lo->hi, hi carry dropped) -----
    const int sbyte = sab & 255;
    const int sh = sbyte >> 4;
    const int sl = sbyte & 15;

    // ---- div path: VERBATIM from round-1 kernel (matched exactly) -------
    float sa = (af > 0.f) ? 1.f : ((af < 0.f) ? -1.f : 0.f);
    float sb = (bf > 0.f) ? 1.f : ((bf < 0.f) ? -1.f : 0.f);
    float sg = sa * sb;
    if (sg == 0.f) sg = 1.f;

    const float aa = fabsf(af);
    const float ba = fabsf(bf);

    const float expo = floorf(log2f(ba + 1e-10f));
    const float p2   = exp2f(expo);
    const float norm = fminf(fmaxf(ba / p2, 0.5f), 0.9999f);

    int seg = (int)floorf((norm - 0.5f) * 128.0f);
    seg = max(0, min(63, seg));
    const float bpl   = 0.5f + (float)seg * 0.0078125f;
    const float vl    = 1.0f / bpl;
    const float vr    = 1.0f / (bpl + 0.0078125f);
    const float slope = (vr - vl) * 128.0f;
    float y = vl + slope * (norm - bpl);

    y = y * (2.0f - norm * y);
    y = y * (2.0f - norm * y);
    y = y / p2;

    const float result = aa * y;
    float cand = rintf(result);
    const float check = cand * ba;
    if (check > aa + 0.5f) cand -= 1.0f;
    const float divres = cand * sg;

    // ---- Write 296 floats = 74 float4 per row, streaming (evict-first) --
    // 64 sum groups: 2 per lane; tail group (gates/div) on lanes 0-9.
    float4* pout = (float4*)(out + (size_t)row * OUT_COLS);

    __stcs(&pout[lane],      sum_group(lane,      sbyte, sh, sl));
    __stcs(&pout[lane + 32], sum_group(lane + 32, sbyte, sh, sl));

    if (lane < 10) {
        const int g0 = lane << 2;          // gate index of element 0
        float4 w;
        w.x = (g0     == io) ? 1.0f : 0.0f;
        w.y = (g0 + 1 == io) ? 1.0f : 0.0f;
        w.z = (g0 + 2 == io) ? 1.0f : 0.0f;
        w.w = (lane == 9) ? divres : ((g0 + 3 == io) ? 1.0f : 0.0f);
        __stcs(&pout[64 + lane], w);
    }
}

extern "C" void kernel_launch(void* const* d_in, const int* in_sizes, int n_in,
                              void* d_out, int out_size)
{
    (void)in_sizes; (void)n_in; (void)out_size;
    const float4* a_oh  = (const float4*)d_in[0];
    const float4* b_oh  = (const float4*)d_in[1];
    const float4* op_oh = (const float4*)d_in[2];
    const float*  a_f   = (const float*)d_in[3];
    const float*  b_f   = (const float*)d_in[4];
    float* out = (float*)d_out;

    // one warp per row: 32768 warps = 4096 blocks x 256 threads
    vm_kernel<<<4096, 256>>>(a_oh, b_oh, op_oh, a_f, b_f, out);
}